// round 6
// baseline (speedup 1.0000x reference)
#include <cuda_runtime.h>

// ---------------------------------------------------------------------------
// StepWiseMLPAutoEncoder — fp32 with packed fma.rn.f32x2
// decoder: persistent kernel, 16-wide n-tiles, 16-way k-split,
//          16-deep register prefetch (MLP=16), L2-scoped activation traffic
// ---------------------------------------------------------------------------

#define BATCH 64
#define SS    1024
#define TT    256
#define HH    64
#define EM    1056
#define DM    1056
#define KC    2048
#define KD1   1088
#define MROWS (BATCH*TT)
#define NBLK  132

typedef unsigned long long u64;

// scratch (device globals) — padded +1024 floats for 16-row prefetch overshoot
__device__ float g_xT[BATCH * TT * SS];
__device__ float g_h1[(size_t)MROWS * EM];
__device__ float g_ctrlT[TT * HH * BATCH + 1024];    // [T,H,B] k-major
__device__ float g_hdT[DM * BATCH + 1024];           // [K,B]
__device__ float g_sbufT[2][SS * BATCH + 1024];      // [S,B] ping-pong
__device__ unsigned g_bar = 0;
__device__ unsigned g_gen = 0;

// ---- packed fp32x2 helpers -------------------------------------------------
__device__ __forceinline__ u64 pk2(float lo, float hi) {
    u64 r; asm("mov.b64 %0, {%1, %2};" : "=l"(r) : "f"(lo), "f"(hi)); return r;
}
__device__ __forceinline__ void fma2(u64& d, u64 a, u64 b) {
    asm("fma.rn.f32x2 %0, %1, %2, %0;" : "+l"(d) : "l"(a), "l"(b));
}
__device__ __forceinline__ void unpk2(u64 v, float& lo, float& hi) {
    asm("mov.b64 {%0, %1}, %2;" : "=f"(lo), "=f"(hi) : "l"(v));
}

// ---------------------------------------------------------------------------
__device__ __forceinline__ void grid_sync(int nb)
{
    __threadfence();
    __syncthreads();
    if (threadIdx.x == 0) {
        volatile unsigned* vgen = &g_gen;
        unsigned my = *vgen;
        if (atomicAdd(&g_bar, 1u) == (unsigned)(nb - 1)) {
            atomicExch(&g_bar, 0u);
            __threadfence();
            atomicExch(&g_gen, my + 1u);
        } else {
            while (*vgen == my) { }
            __threadfence();
        }
    }
    __syncthreads();
}

// ---------------------------------------------------------------------------
// x[b,s,t] -> xT[b,t,s]
// ---------------------------------------------------------------------------
__global__ void transpose_x_kernel(const float* __restrict__ x)
{
    __shared__ float tile[32][33];
    int b  = blockIdx.z;
    int t0 = blockIdx.x * 32;
    int s0 = blockIdx.y * 32;
    const float* xb  = x    + (size_t)b * SS * TT;
    float*       xTb = g_xT + (size_t)b * TT * SS;
    int tx = threadIdx.x, ty = threadIdx.y;
#pragma unroll
    for (int j = 0; j < 32; j += 8)
        tile[ty + j][tx] = xb[(s0 + ty + j) * TT + t0 + tx];
    __syncthreads();
#pragma unroll
    for (int j = 0; j < 32; j += 8)
        xTb[(t0 + ty + j) * SS + s0 + tx] = tile[tx][ty + j];
}

// ---------------------------------------------------------------------------
// Encoder GEMM, 64x64 tile, BK=16, 256 threads, 4m x 4n per thread, f32x2.
// ---------------------------------------------------------------------------
template<int MODE>
__global__ __launch_bounds__(256) void enc_gemm_kernel(
    const float* __restrict__ Bmat, const float* __restrict__ bias)
{
    constexpr int N = (MODE == 0) ? EM : HH;
    constexpr int K = (MODE == 0) ? KC : EM;

    __shared__ float As[16][64];
    __shared__ float Bs[16][64];

    int tid  = threadIdx.x;
    int arow = tid >> 2;
    int acol = (tid & 3) * 4;
    int tn   = tid & 15;
    int tm   = tid >> 4;
    int n0   = blockIdx.x * 64;
    int r0   = blockIdx.y * 64;

    u64 acc2[4][2];
#pragma unroll
    for (int i = 0; i < 4; i++) { acc2[i][0] = 0ULL; acc2[i][1] = 0ULL; }

    int r = r0 + arow;
    const float* aprev = nullptr;
    const float* acur  = nullptr;
    if (MODE == 0) {
        int bb = r >> 8;
        int t  = r & 255;
        acur  = g_xT + ((size_t)((bb << 8) + t)) * SS;
        aprev = (t > 0) ? (acur - SS) : nullptr;
    } else {
        acur = g_h1 + (size_t)r * K;
    }

    for (int kc = 0; kc < K; kc += 16) {
        float4 av = make_float4(0.f, 0.f, 0.f, 0.f);
        int kg = kc + acol;
        if (MODE == 0) {
            if (kg < SS) {
                if (aprev) av = *(const float4*)(aprev + kg);
            } else {
                av = *(const float4*)(acur + kg - SS);
            }
        } else {
            av = *(const float4*)(acur + kg);
        }
        As[acol + 0][arow] = av.x;
        As[acol + 1][arow] = av.y;
        As[acol + 2][arow] = av.z;
        As[acol + 3][arow] = av.w;

#pragma unroll
        for (int it = 0; it < 4; it++) {
            int k = (tid >> 6) + it * 4;
            int n = tid & 63;
            int ng = n0 + n;
            float v = 0.f;
            if (ng < N) v = Bmat[(size_t)(kc + k) * N + ng];
            Bs[k][n] = v;
        }
        __syncthreads();

#pragma unroll
        for (int kk = 0; kk < 16; kk++) {
            float4 a4 = *(const float4*)&As[kk][tm * 4];
            ulonglong2 b2 = *(const ulonglong2*)&Bs[kk][tn * 4];
            u64 d0 = pk2(a4.x, a4.x);
            u64 d1 = pk2(a4.y, a4.y);
            u64 d2 = pk2(a4.z, a4.z);
            u64 d3 = pk2(a4.w, a4.w);
            fma2(acc2[0][0], d0, b2.x); fma2(acc2[0][1], d0, b2.y);
            fma2(acc2[1][0], d1, b2.x); fma2(acc2[1][1], d1, b2.y);
            fma2(acc2[2][0], d2, b2.x); fma2(acc2[2][1], d2, b2.y);
            fma2(acc2[3][0], d3, b2.x); fma2(acc2[3][1], d3, b2.y);
        }
        __syncthreads();
    }

#pragma unroll
    for (int i = 0; i < 4; i++) {
        float c[4];
        unpk2(acc2[i][0], c[0], c[1]);
        unpk2(acc2[i][1], c[2], c[3]);
        int rr = r0 + tm * 4 + i;
#pragma unroll
        for (int j = 0; j < 4; j++) {
            int ng = n0 + tn * 4 + j;
            if (ng < N) {
                float v = c[j] + bias[ng];
                if (MODE == 0) {
                    g_h1[(size_t)rr * EM + ng] = fmaxf(v, 0.f);
                } else {
                    int bb = rr >> 8;
                    int tt = rr & 255;
                    g_ctrlT[(tt * HH + ng) * BATCH + bb] = v;
                }
            }
        }
    }
}

// ---------------------------------------------------------------------------
// Persistent decoder.
// 132 blocks x 512 thr. Block = (n-tile nt = bid>>1, m-half mh = bid&1):
// 16 n-cols x 32 m-rows. 16 warps = 16 k-split groups (1 warp each).
// Thread: 1 m-row, 16 n (8 f32x2 accumulators).
// Inner loop: 16-k super-iterations, 16-deep LDG prefetch (MLP=16).
// All segment lengths are multiples of 16 (no tails).
// ---------------------------------------------------------------------------
#define DEC_SMEM ((KD1*16 + DM*16 + 16*16*32) * 4)

__device__ __forceinline__ void dec_seg(
    u64 acc[8], const float* __restrict__ src, const float* __restrict__ Ws,
    int k0, int nk, int moff)
{
    const float* s = src + moff;
    const ulonglong2* wp = (const ulonglong2*)(Ws + k0 * 16);
    float cur[16];
#pragma unroll
    for (int kk = 0; kk < 16; kk++) cur[kk] = __ldcg(s + 64 * kk);

    for (int i = 0; i < nk; i += 16) {
        s += 1024;
        float nxt[16];
#pragma unroll
        for (int kk = 0; kk < 16; kk++) nxt[kk] = __ldcg(s + 64 * kk); // padded
#pragma unroll
        for (int kk = 0; kk < 16; kk++) {
            u64 ad = pk2(cur[kk], cur[kk]);
            ulonglong2 w0 = wp[0], w1 = wp[1], w2 = wp[2], w3 = wp[3];
            wp += 4;
            fma2(acc[0], ad, w0.x); fma2(acc[1], ad, w0.y);
            fma2(acc[2], ad, w1.x); fma2(acc[3], ad, w1.y);
            fma2(acc[4], ad, w2.x); fma2(acc[5], ad, w2.y);
            fma2(acc[6], ad, w3.x); fma2(acc[7], ad, w3.y);
        }
#pragma unroll
        for (int kk = 0; kk < 16; kk++) cur[kk] = nxt[kk];
    }
}

__global__ __launch_bounds__(512) void dec_persistent_kernel(
    const float* __restrict__ Wd1, const float* __restrict__ bd1,
    const float* __restrict__ Wd2, const float* __restrict__ bd2,
    float* __restrict__ out)
{
    extern __shared__ float sm[];
    float* Ws1 = sm;                        // [KD1][16]
    float* Ws2 = sm + KD1 * 16;             // [DM][16]
    float* red = sm + (KD1 + DM) * 16;      // [16g][16n][32m]

    int tid = threadIdx.x;
    int bid = blockIdx.x;
    int nt  = bid >> 1;          // n-tile 0..65
    int mh  = bid & 1;           // m-half
    int n0  = nt * 16;

    // one-time: cache weight slices k-row-major [k][16]
    for (int i = tid; i < 16 * KD1; i += 512) {
        int k = i >> 4, n = i & 15;
        Ws1[i] = Wd1[(size_t)k * DM + n0 + n];
    }
    if (nt < 64) {
        for (int i = tid; i < 16 * DM; i += 512) {
            int k = i >> 4, n = i & 15;
            Ws2[i] = Wd2[(size_t)k * SS + n0 + n];
        }
    }
    {
        int i = bid * 512 + tid;
        if (i < SS * BATCH) g_sbufT[0][i] = 0.f;
    }

    int g    = tid >> 5;             // k-split group = warp 0..15
    int lane = tid & 31;
    int moff = mh * 32 + lane;       // global batch row
    int en   = tid >> 5;             // epilogue n 0..15
    int em   = tid & 31;             // epilogue m 0..31

    float bv1 = bd1[n0 + en];
    float bv2 = (nt < 64) ? bd2[n0 + en] : 0.f;

    // layer1 segments: g 0..3 -> 80 k (g0 split 64 ctrl + 16 sbuf), g 4..15 -> 64 k
    int kb1  = (g < 4) ? g * 80 : 320 + (g - 4) * 64;
    int nk1  = (g < 4) ? 80 : 64;
    // layer2 segments: g 0..1 -> 80 k, g 2..15 -> 64 k
    int kb2  = (g < 2) ? g * 80 : 160 + (g - 2) * 64;
    int nk2  = (g < 2) ? 80 : 64;

    grid_sync(NBLK);

    for (int t = 0; t < TT; t++) {
        const float* sbT = g_sbufT[t & 1];
        const float* ctrl_base = g_ctrlT + t * HH * BATCH;

        // ---- layer 1: g_hdT = relu([ctrl_t | prev] @ Wd1 + bd1), K=1088
        {
            u64 acc[8] = {};
            if (g == 0) {
                dec_seg(acc, ctrl_base, Ws1, 0, 64, moff);   // k 0..63 (ctrl)
                dec_seg(acc, sbT, Ws1, 64, 16, moff);        // k 64..79 (sbuf 0..15)
            } else {
                dec_seg(acc, sbT + (kb1 - HH) * 64, Ws1, kb1, nk1, moff);
            }
#pragma unroll
            for (int p = 0; p < 8; p++) {
                float lo, hi; unpk2(acc[p], lo, hi);
                red[(g * 16 + 2 * p) * 32 + lane]     = lo;
                red[(g * 16 + 2 * p + 1) * 32 + lane] = hi;
            }
            __syncthreads();

            float v = bv1;
#pragma unroll
            for (int gg = 0; gg < 16; gg++)
                v += red[(gg * 16 + en) * 32 + em];
            __stcg(&g_hdT[(n0 + en) * 64 + mh * 32 + em], fmaxf(v, 0.f));
        }
        grid_sync(NBLK);

        // ---- layer 2: out_t = g_hd @ Wd2 + bd2, K=1056
        if (nt < 64) {
            u64 acc[8] = {};
            dec_seg(acc, g_hdT + kb2 * 64, Ws2, kb2, nk2, moff);
#pragma unroll
            for (int p = 0; p < 8; p++) {
                float lo, hi; unpk2(acc[p], lo, hi);
                red[(g * 16 + 2 * p) * 32 + lane]     = lo;
                red[(g * 16 + 2 * p + 1) * 32 + lane] = hi;
            }
            __syncthreads();

            float v = bv2;
#pragma unroll
            for (int gg = 0; gg < 16; gg++)
                v += red[(gg * 16 + en) * 32 + em];
            int s = n0 + en;
            int m = mh * 32 + em;
            __stcg(&g_sbufT[(t + 1) & 1][s * 64 + m], v);
            out[((size_t)m * SS + s) * TT + t] = v;
        }
        grid_sync(NBLK);
    }
}

// ---------------------------------------------------------------------------
extern "C" void kernel_launch(void* const* d_in, const int* in_sizes, int n_in,
                              void* d_out, int out_size)
{
    const float* x   = (const float*)d_in[0];
    const float* We1 = (const float*)d_in[1];
    const float* be1 = (const float*)d_in[2];
    const float* We2 = (const float*)d_in[3];
    const float* be2 = (const float*)d_in[4];
    const float* Wd1 = (const float*)d_in[5];
    const float* bd1 = (const float*)d_in[6];
    const float* Wd2 = (const float*)d_in[7];
    const float* bd2 = (const float*)d_in[8];
    float* out = (float*)d_out;

    cudaFuncSetAttribute(dec_persistent_kernel,
                         cudaFuncAttributeMaxDynamicSharedMemorySize, DEC_SMEM);

    transpose_x_kernel<<<dim3(TT / 32, SS / 32, BATCH), dim3(32, 8)>>>(x);
    enc_gemm_kernel<0><<<dim3((EM + 63) / 64, MROWS / 64), 256>>>(We1, be1);
    enc_gemm_kernel<1><<<dim3(1, MROWS / 64), 256>>>(We2, be2);

    dec_persistent_kernel<<<NBLK, 512, DEC_SMEM>>>(Wd1, bd1, Wd2, bd2, out);
}